// round 9
// baseline (speedup 1.0000x reference)
#include <cuda_runtime.h>
#include <cuda_fp16.h>
#include <cstdint>

// ============================================================================
// out[m][n] = (sum_k x[m][k] * wq[n][k]) * ws[n];  M=8192, N=4096, K=4096
// R2: harness ptxas targets sm_103 (no 'a') -> no tcgen05; mma.sync HMMA path.
// R6: wire-format autodetect -> PASS. R7/R8: tensor stuck ~72-73% regardless of
//     occupancy -> per-iteration sync overhead + wave transitions, not latency.
// R9: BK=128 / 2 stages (half the barriers) + persistent CTAs (no wave
//     transition bubbles; next-tile loads overlap current epilogue).
// ============================================================================

#define M_DIM 8192
#define N_DIM 4096
#define K_DIM 4096

#define BM 128
#define BN 256
#define BK 128
#define STEPS_PER_TILE (K_DIM / BK)   // 32
#define NTHREADS 512
#define GRID_X 148
#define NTILES ((M_DIM / BM) * (N_DIM / BN))   // 1024

static __device__ __align__(1024) __half g_X16[(size_t)M_DIM * K_DIM];  // 64 MB
static __device__ __align__(1024) __half g_W16[(size_t)N_DIM * K_DIM];  // 32 MB
static __device__ int g_wfmt;  // 0 = int8, 1 = int32, 2 = float32

// ---------------------------------------------------------------------------
// Helpers (all baseline PTX)
// ---------------------------------------------------------------------------
__device__ __forceinline__ uint32_t smem_u32(const void* p) {
    uint32_t a;
    asm("{ .reg .u64 t; cvta.to.shared.u64 t, %1; cvt.u32.u64 %0, t; }"
        : "=r"(a) : "l"(p));
    return a;
}

#define SWZ128(off) ((off) ^ (((off) >> 3) & 0x70))

__device__ __forceinline__ void cp_async16(uint32_t dst, const void* src) {
    asm volatile("cp.async.cg.shared.global [%0], [%1], 16;"
                 :: "r"(dst), "l"(src) : "memory");
}
__device__ __forceinline__ void cp_async_commit() {
    asm volatile("cp.async.commit_group;" ::: "memory");
}
template <int N>
__device__ __forceinline__ void cp_async_wait() {
    asm volatile("cp.async.wait_group %0;" :: "n"(N) : "memory");
}

__device__ __forceinline__ void ldsm_x4(uint32_t addr, uint32_t& r0, uint32_t& r1,
                                        uint32_t& r2, uint32_t& r3) {
    asm volatile("ldmatrix.sync.aligned.m8n8.x4.shared.b16 {%0,%1,%2,%3}, [%4];"
                 : "=r"(r0), "=r"(r1), "=r"(r2), "=r"(r3) : "r"(addr));
}

__device__ __forceinline__ void mma_16816(float* c, const uint32_t* a, const uint32_t* b) {
    asm volatile(
        "mma.sync.aligned.m16n8k16.row.col.f32.f16.f16.f32 "
        "{%0,%1,%2,%3}, {%4,%5,%6,%7}, {%8,%9}, {%0,%1,%2,%3};"
        : "+f"(c[0]), "+f"(c[1]), "+f"(c[2]), "+f"(c[3])
        : "r"(a[0]), "r"(a[1]), "r"(a[2]), "r"(a[3]), "r"(b[0]), "r"(b[1]));
}

// ---------------------------------------------------------------------------
// SMEM layout: 2 stages of 96 KB. Each stage holds A and B split into two
// K-halves of 128B-wide rows (so the SWZ128 ldmatrix layout is unchanged).
//   A stage: [2][128 rows][128 B] = 32 KB     (half h covers k = h*64..h*64+63)
//   B stage: [2][256 rows][128 B] = 64 KB
// ---------------------------------------------------------------------------
static constexpr int STAGE_OFF   = 0;
static constexpr int A_HALF_B    = BM * 128;                // 16384
static constexpr int A_STAGE_B   = 2 * A_HALF_B;            // 32768
static constexpr int B_HALF_B    = BN * 128;                // 32768
static constexpr int B_STAGE_B   = 2 * B_HALF_B;            // 65536
static constexpr int STAGE_BYTES = A_STAGE_B + B_STAGE_B;   // 98304
static constexpr int SMEM_TOTAL  = STAGE_OFF + 2 * STAGE_BYTES;  // 196608

// ---------------------------------------------------------------------------
// Weight wire-format autodetect (parallel, deterministic)
// ---------------------------------------------------------------------------
__global__ void detect_w_fmt_kernel(const void* w) {
    const int t = threadIdx.x;
    const int32_t* wi = (const int32_t*)w;
    const float*   wf = (const float*)w;
    bool i32ok = true, f32ok = true;
    #pragma unroll
    for (int j = 0; j < 8; j++) {
        int i = t * 8 + j;
        int32_t v = wi[i];
        if (v < -127 || v > 127) i32ok = false;
        float f = wf[i];
        if (!isfinite(f) || fabsf(f) > 127.0f || f != rintf(f)) f32ok = false;
    }
    int n_i32 = __syncthreads_count(i32ok);
    int n_f32 = __syncthreads_count(f32ok);
    if (t == 0) g_wfmt = (n_i32 == 256) ? 1 : ((n_f32 == 256) ? 2 : 0);
}

// ---------------------------------------------------------------------------
// Conversion kernels
// ---------------------------------------------------------------------------
__global__ void cvt_x_kernel(const float4* __restrict__ x) {
    int i = blockIdx.x * blockDim.x + threadIdx.x;
    float4 v = x[i];
    __half2* o = reinterpret_cast<__half2*>(g_X16);
    o[i * 2]     = __floats2half2_rn(v.x, v.y);
    o[i * 2 + 1] = __floats2half2_rn(v.z, v.w);
}

__global__ void cvt_w_kernel(const void* __restrict__ w) {
    int i = blockIdx.x * blockDim.x + threadIdx.x;
    const int fmt = g_wfmt;
    float vx, vy, vz, vw;
    if (fmt == 0) {
        char4 c = reinterpret_cast<const char4*>(w)[i];
        vx = (float)c.x; vy = (float)c.y; vz = (float)c.z; vw = (float)c.w;
    } else if (fmt == 1) {
        int4 c = reinterpret_cast<const int4*>(w)[i];
        vx = (float)c.x; vy = (float)c.y; vz = (float)c.z; vw = (float)c.w;
    } else {
        float4 c = reinterpret_cast<const float4*>(w)[i];
        vx = c.x; vy = c.y; vz = c.z; vw = c.w;
    }
    __half2* o = reinterpret_cast<__half2*>(g_W16);
    o[i * 2]     = __floats2half2_rn(vx, vy);
    o[i * 2 + 1] = __floats2half2_rn(vz, vw);
}

// ---------------------------------------------------------------------------
// Persistent GEMM: grid=148 CTAs, each loops over tiles bx, bx+148, ...
// 128x256 CTA tile, 16 warps (2x8) each 64x32, 2-stage BK=128 pipeline.
// ---------------------------------------------------------------------------
__global__ void __launch_bounds__(NTHREADS, 1)
gemm_hmma_kernel(const float* __restrict__ scaler, float* __restrict__ out) {
    extern __shared__ char smem[];
    const uint32_t smem_base = smem_u32(smem);
    const int tid = threadIdx.x;
    const int wid = tid >> 5;
    const int lid = tid & 31;
    const int bx = blockIdx.x;

    const int n_tiles = (NTILES - bx + GRID_X - 1) / GRID_X;
    const int n_steps = n_tiles * STEPS_PER_TILE;

    const int wm = (wid >> 3) * 64;   // 2 warp rows of 64
    const int wn = (wid & 7) * 32;    // 8 warp cols of 32

    // cp.async loads for flat step s (stage = s&1); always commits a group.
    auto load_step = [&](int s) {
        if (s < n_steps) {
            const int tile = bx + (s >> 5) * GRID_X;
            const int it = s & 31;
            const int m0 = (tile >> 4) << 7;
            const int n0 = (tile & 15) << 8;
            const int kt = it << 7;
            const uint32_t sbase = smem_base + STAGE_OFF + (s & 1) * STAGE_BYTES;
            #pragma unroll
            for (int j = 0; j < 4; j++) {          // A: 2048 x 16B chunks
                int id = tid + NTHREADS * j;
                int h = id >> 10, rem = id & 1023;
                int r = rem >> 3, c2 = rem & 7;
                const __half* gp = g_X16 + (size_t)(m0 + r) * K_DIM + kt + h * 64 + c2 * 8;
                cp_async16(sbase + h * A_HALF_B + SWZ128(r * 128 + c2 * 16), gp);
            }
            #pragma unroll
            for (int j = 0; j < 8; j++) {          // B: 4096 x 16B chunks
                int id = tid + NTHREADS * j;
                int h = id >> 11, rem = id & 2047;
                int r = rem >> 3, c2 = rem & 7;
                const __half* gp = g_W16 + (size_t)(n0 + r) * K_DIM + kt + h * 64 + c2 * 8;
                cp_async16(sbase + A_STAGE_B + h * B_HALF_B + SWZ128(r * 128 + c2 * 16), gp);
            }
        }
        cp_async_commit();
    };

    load_step(0);   // prologue: fill stage 0

    float c[4][4][4];
    #pragma unroll
    for (int i = 0; i < 4; i++)
        #pragma unroll
        for (int j = 0; j < 4; j++)
            #pragma unroll
            for (int k = 0; k < 4; k++) c[i][j][k] = 0.0f;

    // A x4: lanes 0-15 -> rows 0-15 @ +0B, lanes 16-31 -> rows 0-15 @ +16B
    const int a_row = wm + (lid & 15);
    const int a_byt = (lid >> 4) * 16;
    // B x4 (non-trans, [n][k]): 0-7: n0-7@+0 | 8-15: n0-7@+16 | 16-23: n8-15@+0 | 24-31: n8-15@+16
    const int b_row = wn + (lid & 7) + ((lid >> 4) << 3);
    const int b_byt = ((lid >> 3) & 1) * 16;

    #pragma unroll 1
    for (int s = 0; s < n_steps; ++s) {
        cp_async_wait<0>();      // stage s&1 landed (issued at step s-1)
        __syncthreads();         // also WAR: all warps done reading stage (s+1)&1
        load_step(s + 1);        // fill the other stage

        const uint32_t abase = smem_base + STAGE_OFF + (s & 1) * STAGE_BYTES;
        const uint32_t bbase = abase + A_STAGE_B;

        #pragma unroll
        for (int ks = 0; ks < 8; ks++) {      // BK=128 -> 8 k16 steps
            const uint32_t hoffA = (ks >> 2) * A_HALF_B;
            const uint32_t hoffB = (ks >> 2) * B_HALF_B;
            const int kb = (ks & 3) * 32;
            uint32_t a[4][4];
            #pragma unroll
            for (int mt = 0; mt < 4; mt++) {
                uint32_t addr = abase + hoffA + SWZ128((a_row + mt * 16) * 128 + kb + a_byt);
                ldsm_x4(addr, a[mt][0], a[mt][1], a[mt][2], a[mt][3]);
            }
            uint32_t b[4][2];
            #pragma unroll
            for (int np = 0; np < 2; np++) {
                uint32_t r0, r1, r2, r3;
                uint32_t addr = bbase + hoffB + SWZ128((b_row + np * 16) * 128 + kb + b_byt);
                ldsm_x4(addr, r0, r1, r2, r3);
                b[np * 2][0] = r0;     b[np * 2][1] = r1;
                b[np * 2 + 1][0] = r2; b[np * 2 + 1][1] = r3;
            }
            #pragma unroll
            for (int mt = 0; mt < 4; mt++)
                #pragma unroll
                for (int nt = 0; nt < 4; nt++)
                    mma_16816(c[mt][nt], a[mt], b[nt]);
        }

        if ((s & 31) == 31) {
            // ---- epilogue for the tile just finished (loads for next tile
            //      are already in flight, overlapping these stores) ----
            const int tile = bx + (s >> 5) * GRID_X;
            const int m0 = (tile >> 4) << 7;
            const int n0 = (tile & 15) << 8;
            const int row_base = m0 + wm + (lid >> 2);
            const int col_base = n0 + wn + (lid & 3) * 2;
            #pragma unroll
            for (int mt = 0; mt < 4; mt++) {
                #pragma unroll
                for (int nt = 0; nt < 4; nt++) {
                    const int cl = col_base + nt * 8;
                    const float s0 = __ldg(scaler + cl);
                    const float s1 = __ldg(scaler + cl + 1);
                    const int gr0 = row_base + mt * 16;
                    float* p0 = out + (size_t)gr0 * N_DIM + cl;
                    float* p1 = p0 + (size_t)8 * N_DIM;
                    float2 v0 = make_float2(c[mt][nt][0] * s0, c[mt][nt][1] * s1);
                    float2 v1 = make_float2(c[mt][nt][2] * s0, c[mt][nt][3] * s1);
                    *reinterpret_cast<float2*>(p0) = v0;
                    *reinterpret_cast<float2*>(p1) = v1;
                    c[mt][nt][0] = 0.0f; c[mt][nt][1] = 0.0f;
                    c[mt][nt][2] = 0.0f; c[mt][nt][3] = 0.0f;
                }
            }
        }
    }
}

// ---------------------------------------------------------------------------
// Launch: dispatch inputs by element count, not position.
// ---------------------------------------------------------------------------
extern "C" void kernel_launch(void* const* d_in, const int* in_sizes, int n_in,
                              void* d_out, int out_size) {
    const void* px = d_in[0];
    const void* pw = d_in[1];
    const void* ps = d_in[2];
    for (int i = 0; i < n_in; i++) {
        if (in_sizes[i] == 33554432)       px = d_in[i];
        else if (in_sizes[i] == 16777216)  pw = d_in[i];
        else if (in_sizes[i] == 4096)      ps = d_in[i];
    }
    float* out = (float*)d_out;

    detect_w_fmt_kernel<<<1, 256>>>(pw);
    cvt_x_kernel<<<(int)((size_t)M_DIM * K_DIM / 4 / 256), 256>>>((const float4*)px);
    cvt_w_kernel<<<(int)((size_t)N_DIM * K_DIM / 4 / 256), 256>>>(pw);

    cudaFuncSetAttribute(gemm_hmma_kernel,
                         cudaFuncAttributeMaxDynamicSharedMemorySize, SMEM_TOTAL);
    gemm_hmma_kernel<<<GRID_X, NTHREADS, SMEM_TOTAL>>>((const float*)ps, out);
}

// round 10
// speedup vs baseline: 1.0954x; 1.0954x over previous
#include <cuda_runtime.h>
#include <cuda_fp16.h>
#include <cstdint>

// ============================================================================
// out[m][n] = (sum_k x[m][k] * wq[n][k]) * ws[n];  M=8192, N=4096, K=4096
// R2: harness ptxas targets sm_103 (no 'a') -> no tcgen05; mma.sync HMMA path.
// R6: wire-format autodetect -> PASS. R7/R8: tensor ~73%; busy cycles == HMMA
//     floor -> remaining 27% is CTA-wide barrier/wave idle with 1 CTA/SM.
// R9: 2-stage BK=128 regressed (no pipeline slack). REVERTED.
// R10: 2 CTAs/SM: BM=BN=128, 256 thr/CTA, 3-stage BK=64 (96 KB/CTA),
//      launch_bounds(256,2) -> independent barriers cover each other's stalls.
// ============================================================================

#define M_DIM 8192
#define N_DIM 4096
#define K_DIM 4096

#define BM 128
#define BN 128
#define BK 64
#define STAGES 3
#define KITERS (K_DIM / BK)   // 64
#define NTHREADS 256

static __device__ __align__(1024) __half g_X16[(size_t)M_DIM * K_DIM];  // 64 MB
static __device__ __align__(1024) __half g_W16[(size_t)N_DIM * K_DIM];  // 32 MB
static __device__ int g_wfmt;  // 0 = int8, 1 = int32, 2 = float32

// ---------------------------------------------------------------------------
// Helpers (all baseline PTX)
// ---------------------------------------------------------------------------
__device__ __forceinline__ uint32_t smem_u32(const void* p) {
    uint32_t a;
    asm("{ .reg .u64 t; cvta.to.shared.u64 t, %1; cvt.u32.u64 %0, t; }"
        : "=r"(a) : "l"(p));
    return a;
}

#define SWZ128(off) ((off) ^ (((off) >> 3) & 0x70))

__device__ __forceinline__ void cp_async16(uint32_t dst, const void* src) {
    asm volatile("cp.async.cg.shared.global [%0], [%1], 16;"
                 :: "r"(dst), "l"(src) : "memory");
}
__device__ __forceinline__ void cp_async_commit() {
    asm volatile("cp.async.commit_group;" ::: "memory");
}
template <int N>
__device__ __forceinline__ void cp_async_wait() {
    asm volatile("cp.async.wait_group %0;" :: "n"(N) : "memory");
}

__device__ __forceinline__ void ldsm_x4(uint32_t addr, uint32_t& r0, uint32_t& r1,
                                        uint32_t& r2, uint32_t& r3) {
    asm volatile("ldmatrix.sync.aligned.m8n8.x4.shared.b16 {%0,%1,%2,%3}, [%4];"
                 : "=r"(r0), "=r"(r1), "=r"(r2), "=r"(r3) : "r"(addr));
}

__device__ __forceinline__ void mma_16816(float* c, const uint32_t* a, const uint32_t* b) {
    asm volatile(
        "mma.sync.aligned.m16n8k16.row.col.f32.f16.f16.f32 "
        "{%0,%1,%2,%3}, {%4,%5,%6,%7}, {%8,%9}, {%0,%1,%2,%3};"
        : "+f"(c[0]), "+f"(c[1]), "+f"(c[2]), "+f"(c[3])
        : "r"(a[0]), "r"(a[1]), "r"(a[2]), "r"(a[3]), "r"(b[0]), "r"(b[1]));
}

// ---------------------------------------------------------------------------
// SMEM layout: 3 stages x (A 16KB + B 16KB) = 96 KB per CTA
// ---------------------------------------------------------------------------
static constexpr int A_STAGE_B   = BM * 128;                // 16 KB
static constexpr int B_STAGE_B   = BN * 128;                // 16 KB
static constexpr int STAGE_BYTES = A_STAGE_B + B_STAGE_B;   // 32 KB
static constexpr int SMEM_TOTAL  = STAGES * STAGE_BYTES;    // 96 KB

// ---------------------------------------------------------------------------
// Weight wire-format autodetect (parallel, deterministic)
// ---------------------------------------------------------------------------
__global__ void detect_w_fmt_kernel(const void* w) {
    const int t = threadIdx.x;
    const int32_t* wi = (const int32_t*)w;
    const float*   wf = (const float*)w;
    bool i32ok = true, f32ok = true;
    #pragma unroll
    for (int j = 0; j < 8; j++) {
        int i = t * 8 + j;
        int32_t v = wi[i];
        if (v < -127 || v > 127) i32ok = false;
        float f = wf[i];
        if (!isfinite(f) || fabsf(f) > 127.0f || f != rintf(f)) f32ok = false;
    }
    int n_i32 = __syncthreads_count(i32ok);
    int n_f32 = __syncthreads_count(f32ok);
    if (t == 0) g_wfmt = (n_i32 == 256) ? 1 : ((n_f32 == 256) ? 2 : 0);
}

// ---------------------------------------------------------------------------
// Conversion kernels
// ---------------------------------------------------------------------------
__global__ void cvt_x_kernel(const float4* __restrict__ x) {
    int i = blockIdx.x * blockDim.x + threadIdx.x;
    float4 v = x[i];
    __half2* o = reinterpret_cast<__half2*>(g_X16);
    o[i * 2]     = __floats2half2_rn(v.x, v.y);
    o[i * 2 + 1] = __floats2half2_rn(v.z, v.w);
}

__global__ void cvt_w_kernel(const void* __restrict__ w) {
    int i = blockIdx.x * blockDim.x + threadIdx.x;
    const int fmt = g_wfmt;
    float vx, vy, vz, vw;
    if (fmt == 0) {
        char4 c = reinterpret_cast<const char4*>(w)[i];
        vx = (float)c.x; vy = (float)c.y; vz = (float)c.z; vw = (float)c.w;
    } else if (fmt == 1) {
        int4 c = reinterpret_cast<const int4*>(w)[i];
        vx = (float)c.x; vy = (float)c.y; vz = (float)c.z; vw = (float)c.w;
    } else {
        float4 c = reinterpret_cast<const float4*>(w)[i];
        vx = c.x; vy = c.y; vz = c.z; vw = c.w;
    }
    __half2* o = reinterpret_cast<__half2*>(g_W16);
    o[i * 2]     = __floats2half2_rn(vx, vy);
    o[i * 2 + 1] = __floats2half2_rn(vz, vw);
}

// ---------------------------------------------------------------------------
// GEMM: 128x128 CTA tile, 8 warps (2x4) each 64x32, 3-stage cp.async pipeline,
// 2 CTAs resident per SM (independent barriers cover each other's stalls).
// ---------------------------------------------------------------------------
__global__ void __launch_bounds__(NTHREADS, 2)
gemm_hmma_kernel(const float* __restrict__ scaler, float* __restrict__ out) {
    extern __shared__ char smem[];
    const uint32_t smem_base = smem_u32(smem);
    const int tid = threadIdx.x;
    const int wid = tid >> 5;
    const int lid = tid & 31;

    const int nt_blk = blockIdx.x & 31;     // 32 tiles of 128 cols
    const int mt_blk = blockIdx.x >> 5;     // 64 tiles of 128 rows
    const int m0 = mt_blk * BM;
    const int n0 = nt_blk * BN;

    const int wm = (wid >> 2) * 64;   // 2 warp rows of 64
    const int wn = (wid & 3) * 32;    // 4 warp cols of 32

    auto load_stage = [&](int it) {
        if (it < KITERS) {
            const int kt = it * BK;
            const uint32_t sbase = smem_base + (it % STAGES) * STAGE_BYTES;
            #pragma unroll
            for (int j = 0; j < 4; j++) {          // A: 1024 x 16B chunks
                int id = tid + NTHREADS * j;
                int r = id >> 3, c2 = id & 7;
                const __half* gp = g_X16 + (size_t)(m0 + r) * K_DIM + kt + c2 * 8;
                cp_async16(sbase + SWZ128(r * 128 + c2 * 16), gp);
            }
            #pragma unroll
            for (int j = 0; j < 4; j++) {          // B: 1024 x 16B chunks
                int id = tid + NTHREADS * j;
                int r = id >> 3, c2 = id & 7;
                const __half* gp = g_W16 + (size_t)(n0 + r) * K_DIM + kt + c2 * 8;
                cp_async16(sbase + A_STAGE_B + SWZ128(r * 128 + c2 * 16), gp);
            }
        }
        cp_async_commit();
    };

    #pragma unroll
    for (int s = 0; s < STAGES - 1; s++) load_stage(s);

    float c[4][4][4];
    #pragma unroll
    for (int i = 0; i < 4; i++)
        #pragma unroll
        for (int j = 0; j < 4; j++)
            #pragma unroll
            for (int k = 0; k < 4; k++) c[i][j][k] = 0.0f;

    // A x4: lanes 0-15 -> rows 0-15 @ +0B, lanes 16-31 -> rows 0-15 @ +16B
    const int a_row = wm + (lid & 15);
    const int a_byt = (lid >> 4) * 16;
    // B x4 (non-trans, [n][k]): 0-7: n0-7@+0 | 8-15: n0-7@+16 | 16-23: n8-15@+0 | 24-31: n8-15@+16
    const int b_row = wn + (lid & 7) + ((lid >> 4) << 3);
    const int b_byt = ((lid >> 3) & 1) * 16;

    #pragma unroll 1
    for (int it = 0; it < KITERS; ++it) {
        cp_async_wait<STAGES - 2>();
        __syncthreads();

        const uint32_t abase = smem_base + (it % STAGES) * STAGE_BYTES;
        const uint32_t bbase = abase + A_STAGE_B;

        load_stage(it + STAGES - 1);

        #pragma unroll
        for (int ks = 0; ks < 4; ks++) {      // BK=64 -> 4 k16 steps
            const int kb = ks * 32;
            uint32_t a[4][4];
            #pragma unroll
            for (int mt = 0; mt < 4; mt++) {
                uint32_t addr = abase + SWZ128((a_row + mt * 16) * 128 + kb + a_byt);
                ldsm_x4(addr, a[mt][0], a[mt][1], a[mt][2], a[mt][3]);
            }
            uint32_t b[4][2];
            #pragma unroll
            for (int np = 0; np < 2; np++) {
                uint32_t r0, r1, r2, r3;
                uint32_t addr = bbase + SWZ128((b_row + np * 16) * 128 + kb + b_byt);
                ldsm_x4(addr, r0, r1, r2, r3);
                b[np * 2][0] = r0;     b[np * 2][1] = r1;
                b[np * 2 + 1][0] = r2; b[np * 2 + 1][1] = r3;
            }
            #pragma unroll
            for (int mt = 0; mt < 4; mt++)
                #pragma unroll
                for (int nt = 0; nt < 4; nt++)
                    mma_16816(c[mt][nt], a[mt], b[nt]);
        }
    }

    // --- epilogue: scale per output column, vectorized stores ---
    const int row_base = m0 + wm + (lid >> 2);
    const int col_base = n0 + wn + (lid & 3) * 2;
    #pragma unroll
    for (int mt = 0; mt < 4; mt++) {
        #pragma unroll
        for (int nt = 0; nt < 4; nt++) {
            const int cl = col_base + nt * 8;
            const float s0 = __ldg(scaler + cl);
            const float s1 = __ldg(scaler + cl + 1);
            const int gr0 = row_base + mt * 16;
            float* p0 = out + (size_t)gr0 * N_DIM + cl;
            float* p1 = p0 + (size_t)8 * N_DIM;
            float2 v0 = make_float2(c[mt][nt][0] * s0, c[mt][nt][1] * s1);
            float2 v1 = make_float2(c[mt][nt][2] * s0, c[mt][nt][3] * s1);
            *reinterpret_cast<float2*>(p0) = v0;
            *reinterpret_cast<float2*>(p1) = v1;
        }
    }
}

// ---------------------------------------------------------------------------
// Launch: dispatch inputs by element count, not position.
// ---------------------------------------------------------------------------
extern "C" void kernel_launch(void* const* d_in, const int* in_sizes, int n_in,
                              void* d_out, int out_size) {
    const void* px = d_in[0];
    const void* pw = d_in[1];
    const void* ps = d_in[2];
    for (int i = 0; i < n_in; i++) {
        if (in_sizes[i] == 33554432)       px = d_in[i];
        else if (in_sizes[i] == 16777216)  pw = d_in[i];
        else if (in_sizes[i] == 4096)      ps = d_in[i];
    }
    float* out = (float*)d_out;

    detect_w_fmt_kernel<<<1, 256>>>(pw);
    cvt_x_kernel<<<(int)((size_t)M_DIM * K_DIM / 4 / 256), 256>>>((const float4*)px);
    cvt_w_kernel<<<(int)((size_t)N_DIM * K_DIM / 4 / 256), 256>>>(pw);

    cudaFuncSetAttribute(gemm_hmma_kernel,
                         cudaFuncAttributeMaxDynamicSharedMemorySize, SMEM_TOTAL);
    gemm_hmma_kernel<<<(M_DIM / BM) * (N_DIM / BN), NTHREADS, SMEM_TOTAL>>>(
        (const float*)ps, out);
}